// round 1
// baseline (speedup 1.0000x reference)
#include <cuda_runtime.h>
#include <math.h>

#define NBR   4
#define Dd    256
#define SDIM  64
#define MEAS  320      // Dd + SDIM
#define MH    128
#define RH    64
#define UD    16
#define NOBS  25
#define BSZ   32768
#define HALL  512      // NBR * MH
#define TB    32

// strides (floats)
#define SX_STR 322
#define SH_STR 516
#define SW1_STR 132
#define SW2_STR 260
#define SZ_STR 260

// scratch (constant-folded weights), recomputed every launch
__device__ float g_W1eff[HALL * MEAS];      // [512][320] row-major, gate folded in
__device__ float g_M[NBR * Dd * RH];        // Wout @ Bg   [n][256][64]
__device__ float g_Mu[Dd * UD];             // sum_n Wout @ Bu  [256][16]
__device__ float g_P[Dd * HALL];            // [d][n*128+h] = (Wout Bg W2)
__device__ float g_zbias[Dd];               // sum_n Wout Bg b2

__global__ void pre_w1eff(const float* __restrict__ W1, const float* __restrict__ gates) {
    int e = blockIdx.x * 256 + threadIdx.x;
    if (e >= HALL * MEAS) return;
    int row = e / MEAS, k = e % MEAS;
    int n = row >> 7;
    float scale = 1.f;
    if (k < Dd) scale = 1.f / (1.f + expf(-gates[n * Dd + k]));
    g_W1eff[e] = W1[e] * scale;
}

__global__ void pre_M_Mu(const float* __restrict__ Wout, const float* __restrict__ Bmat) {
    int e = blockIdx.x * 256 + threadIdx.x;
    if (e < NBR * Dd * RH) {
        int n = e / (Dd * RH);
        int rem = e % (Dd * RH);
        int d = rem / RH, j = rem % RH;
        const float* wr = Wout + (n * Dd + d) * RH;
        const float* br = Bmat + n * RH * (RH + UD) + j;
        float s = 0.f;
        #pragma unroll 8
        for (int r = 0; r < RH; r++) s += wr[r] * br[r * (RH + UD)];
        g_M[e] = s;
    } else {
        int e2 = e - NBR * Dd * RH;
        if (e2 < Dd * UD) {
            int d = e2 / UD, u = e2 % UD;
            float s = 0.f;
            for (int n = 0; n < NBR; n++) {
                const float* wr = Wout + (n * Dd + d) * RH;
                const float* br = Bmat + n * RH * (RH + UD) + RH + u;
                #pragma unroll 8
                for (int r = 0; r < RH; r++) s += wr[r] * br[r * (RH + UD)];
            }
            g_Mu[e2] = s;
        }
    }
}

__global__ void pre_P_zb(const float* __restrict__ W2, const float* __restrict__ b2) {
    int e = blockIdx.x * 256 + threadIdx.x;
    if (e < NBR * Dd * MH) {
        int n = e / (Dd * MH);
        int rem = e % (Dd * MH);
        int d = rem / MH, h = rem % MH;
        const float* m = g_M + (n * Dd + d) * RH;
        const float* w = W2 + n * RH * MH + h;
        float s = 0.f;
        #pragma unroll 8
        for (int j = 0; j < RH; j++) s += m[j] * w[j * MH];
        g_P[d * HALL + n * MH + h] = s;
    } else if (e < NBR * Dd * MH + Dd) {
        int d = e - NBR * Dd * MH;
        float s = 0.f;
        for (int n = 0; n < NBR; n++) {
            const float* m = g_M + (n * Dd + d) * RH;
            const float* bb = b2 + n * RH;
            #pragma unroll 8
            for (int j = 0; j < RH; j++) s += m[j] * bb[j];
        }
        g_zbias[d] = s;
    }
}

__global__ __launch_bounds__(256, 1) void skolr_main(
    const float* __restrict__ z_dyn, const float* __restrict__ z_static,
    const float* __restrict__ dtp,   const float* __restrict__ ut,
    const float* __restrict__ b1,    const float* __restrict__ gamma,
    const float* __restrict__ beta,  const float* __restrict__ Cmat,
    const float* __restrict__ Dm,    float* __restrict__ out)
{
    extern __shared__ float sm[];
    float* s_h = sm;                           // TB * 516
    float* s_w = s_h + TB * SH_STR;            // TB tile weights: up to 32*260
    float* s_u = s_w + 32 * SW2_STR;           // TB * 16
    float* s_x = s_u + TB * UD;                // TB * 322 ; later aliased as s_z
    float* s_z = s_x;                          // TB * 260 (alias, used after GEMM1)

    const int tid = threadIdx.x;
    const int row0 = blockIdx.x * TB;
    const float dt = dtp[0];

    // ---- load x = [z_dyn ; z_static], and u*dt ----
    for (int idx = tid; idx < TB * MEAS; idx += 256) {
        int r = idx / MEAS, k = idx % MEAS;
        float v = (k < Dd) ? z_dyn[(size_t)(row0 + r) * Dd + k]
                           : z_static[(size_t)(row0 + r) * SDIM + (k - Dd)];
        s_x[r * SX_STR + k] = v;
    }
    for (int idx = tid; idx < TB * UD; idx += 256) {
        int r = idx / UD, u = idx % UD;
        s_u[idx] = ut[(size_t)(row0 + r) * UD + u] * dt;
    }
    __syncthreads();

    const int tr = tid >> 5;          // warp id: row group (4 rows)
    const int lane = tid & 31;
    const int r0 = tr * 4;

    // ================= GEMM1 per branch: h = W1eff @ x + b1 -> LN -> GELU =================
    for (int n = 0; n < NBR; n++) {
        const int c0 = lane * 4;      // 32 lanes * 4 cols = 128
        float acc[4][4];
        #pragma unroll
        for (int i = 0; i < 4; i++)
            #pragma unroll
            for (int j = 0; j < 4; j++) acc[i][j] = 0.f;

        for (int kt = 0; kt < MEAS; kt += 32) {
            __syncthreads();
            // stage W1eff tile [128 cols][32 k] transposed into s_w[kk][c]
            for (int idx = tid; idx < MH * 32; idx += 256) {
                int c = idx >> 5, kk = idx & 31;
                s_w[kk * SW1_STR + c] = g_W1eff[(n * MH + c) * MEAS + kt + kk];
            }
            __syncthreads();
            #pragma unroll 8
            for (int kk = 0; kk < 32; kk++) {
                float xr[4];
                #pragma unroll
                for (int i = 0; i < 4; i++) xr[i] = s_x[(r0 + i) * SX_STR + kt + kk];
                float4 w4 = *(const float4*)&s_w[kk * SW1_STR + c0];
                #pragma unroll
                for (int i = 0; i < 4; i++) {
                    acc[i][0] = fmaf(xr[i], w4.x, acc[i][0]);
                    acc[i][1] = fmaf(xr[i], w4.y, acc[i][1]);
                    acc[i][2] = fmaf(xr[i], w4.z, acc[i][2]);
                    acc[i][3] = fmaf(xr[i], w4.w, acc[i][3]);
                }
            }
        }

        // bias + LayerNorm (warp covers the full 128-wide row) + GELU(exact)
        float b1v[4], gv[4], bev[4];
        #pragma unroll
        for (int j = 0; j < 4; j++) {
            b1v[j] = b1[n * MH + c0 + j];
            gv[j]  = gamma[n * MH + c0 + j];
            bev[j] = beta[n * MH + c0 + j];
        }
        #pragma unroll
        for (int i = 0; i < 4; i++) {
            float s = 0.f, ss = 0.f;
            #pragma unroll
            for (int j = 0; j < 4; j++) {
                acc[i][j] += b1v[j];
                s += acc[i][j];
                ss = fmaf(acc[i][j], acc[i][j], ss);
            }
            #pragma unroll
            for (int o = 16; o > 0; o >>= 1) {
                s  += __shfl_xor_sync(0xffffffffu, s, o);
                ss += __shfl_xor_sync(0xffffffffu, ss, o);
            }
            float mean = s * (1.f / 128.f);
            float var  = ss * (1.f / 128.f) - mean * mean;
            float inv  = rsqrtf(var + 1e-5f);
            float4 hv;
            float* hvp = &hv.x;
            #pragma unroll
            for (int j = 0; j < 4; j++) {
                float v = (acc[i][j] - mean) * inv * gv[j] + bev[j];
                v = 0.5f * v * (1.f + erff(v * 0.70710678118654752f));
                hvp[j] = v;
            }
            *(float4*)&s_h[(r0 + i) * SH_STR + n * MH + c0] = hv;
        }
    }

    // ================= GEMM2: z = P @ h_gelu  (+ zbias + Mu u) =================
    const int c0b = lane * 8;         // 32 lanes * 8 cols = 256
    float acc2[4][8];
    #pragma unroll
    for (int i = 0; i < 4; i++)
        #pragma unroll
        for (int j = 0; j < 8; j++) acc2[i][j] = 0.f;

    for (int kt = 0; kt < HALL; kt += 32) {
        __syncthreads();
        for (int idx = tid; idx < Dd * 32; idx += 256) {
            int d = idx >> 5, kk = idx & 31;
            s_w[kk * SW2_STR + d] = g_P[d * HALL + kt + kk];
        }
        __syncthreads();
        #pragma unroll 8
        for (int kk = 0; kk < 32; kk++) {
            float hr[4];
            #pragma unroll
            for (int i = 0; i < 4; i++) hr[i] = s_h[(r0 + i) * SH_STR + kt + kk];
            float4 wa = *(const float4*)&s_w[kk * SW2_STR + c0b];
            float4 wb = *(const float4*)&s_w[kk * SW2_STR + c0b + 4];
            #pragma unroll
            for (int i = 0; i < 4; i++) {
                acc2[i][0] = fmaf(hr[i], wa.x, acc2[i][0]);
                acc2[i][1] = fmaf(hr[i], wa.y, acc2[i][1]);
                acc2[i][2] = fmaf(hr[i], wa.z, acc2[i][2]);
                acc2[i][3] = fmaf(hr[i], wa.w, acc2[i][3]);
                acc2[i][4] = fmaf(hr[i], wb.x, acc2[i][4]);
                acc2[i][5] = fmaf(hr[i], wb.y, acc2[i][5]);
                acc2[i][6] = fmaf(hr[i], wb.z, acc2[i][6]);
                acc2[i][7] = fmaf(hr[i], wb.w, acc2[i][7]);
            }
        }
    }
    __syncthreads();   // done reading s_x / s_w; s_z (alias of s_x) now writable

    // epilogue: z = acc2 + zbias + Mu @ u ; write z_next
    #pragma unroll
    for (int i = 0; i < 4; i++) {
        int r = r0 + i;
        float uu[UD];
        #pragma unroll
        for (int q = 0; q < UD; q++) uu[q] = s_u[r * UD + q];
        #pragma unroll
        for (int j = 0; j < 8; j++) {
            int d = c0b + j;
            float v = acc2[i][j] + g_zbias[d];
            const float4* mu4 = (const float4*)&g_Mu[d * UD];
            #pragma unroll
            for (int q4 = 0; q4 < 4; q4++) {
                float4 m = mu4[q4];
                v = fmaf(m.x, uu[q4 * 4 + 0], v);
                v = fmaf(m.y, uu[q4 * 4 + 1], v);
                v = fmaf(m.z, uu[q4 * 4 + 2], v);
                v = fmaf(m.w, uu[q4 * 4 + 3], v);
            }
            s_z[r * SZ_STR + d] = v;
            out[(size_t)(row0 + r) * Dd + d] = v;
        }
    }
    __syncthreads();

    // ================= yt = z @ C^T + (u*dt) @ D^T =================
    float* out_yt = out + (size_t)BSZ * Dd;
    for (int idx = tid; idx < TB * NOBS; idx += 256) {
        int r = idx / NOBS, o = idx % NOBS;
        const float4* cr = (const float4*)(Cmat + o * Dd);
        const float4* zr = (const float4*)(s_z + r * SZ_STR);
        float s = 0.f;
        #pragma unroll 8
        for (int k = 0; k < Dd / 4; k++) {
            float4 z4 = zr[k];
            float4 c4 = cr[k];
            s = fmaf(z4.x, c4.x, s);
            s = fmaf(z4.y, c4.y, s);
            s = fmaf(z4.z, c4.z, s);
            s = fmaf(z4.w, c4.w, s);
        }
        #pragma unroll
        for (int q = 0; q < UD; q++) s = fmaf(s_u[r * UD + q], Dm[o * UD + q], s);
        out_yt[(size_t)(row0 + r) * NOBS + o] = s;
    }
}

extern "C" void kernel_launch(void* const* d_in, const int* in_sizes, int n_in,
                              void* d_out, int out_size) {
    const float* z_dyn    = (const float*)d_in[0];
    const float* z_static = (const float*)d_in[1];
    const float* dt       = (const float*)d_in[2];
    const float* ut       = (const float*)d_in[3];
    const float* gates    = (const float*)d_in[4];
    const float* W1       = (const float*)d_in[5];
    const float* b1       = (const float*)d_in[6];
    const float* gamma    = (const float*)d_in[7];
    const float* beta     = (const float*)d_in[8];
    const float* W2       = (const float*)d_in[9];
    const float* b2       = (const float*)d_in[10];
    // d_in[11] lam_real, d_in[12] lam_imag: dead (h0 == 0)
    const float* Bmat     = (const float*)d_in[13];
    const float* Wout     = (const float*)d_in[14];
    const float* Cmat     = (const float*)d_in[15];
    const float* Dm       = (const float*)d_in[16];
    float* out = (float*)d_out;

    // precompute folded weights (tiny; runs every call, deterministic)
    pre_w1eff<<<(HALL * MEAS + 255) / 256, 256>>>(W1, gates);
    pre_M_Mu<<<(NBR * Dd * RH + Dd * UD + 255) / 256, 256>>>(Wout, Bmat);
    pre_P_zb<<<(NBR * Dd * MH + Dd + 255) / 256, 256>>>(W2, b2);

    const int smem_bytes = (TB * SH_STR + 32 * SW2_STR + TB * UD + TB * SX_STR) * sizeof(float);
    cudaFuncSetAttribute(skolr_main, cudaFuncAttributeMaxDynamicSharedMemorySize, smem_bytes);
    skolr_main<<<BSZ / TB, 256, smem_bytes>>>(
        z_dyn, z_static, dt, ut, b1, gamma, beta, Cmat, Dm, out);
}

// round 2
// speedup vs baseline: 2.1007x; 2.1007x over previous
#include <cuda_runtime.h>
#include <cuda_bf16.h>
#include <math.h>

#define NBR   4
#define Dd    256
#define SDIM  64
#define MEAS  320
#define MH    128
#define RH    64
#define UD    16
#define NOBS  25
#define BSZ   32768
#define HALL  512          // NBR*MH
#define K2    528          // HALL + UD
#define N2    288          // Dd + 32 (25 yt cols padded)
#define TM    64           // rows per CTA

// ---- device scratch (recomputed every launch; no allocs) ----
__device__ __nv_bfloat16 g_W1h[HALL * MEAS];
__device__ __nv_bfloat16 g_W1l[HALL * MEAS];
__device__ float g_M[NBR * Dd * RH];
__device__ float g_Mu[Dd * UD];
__device__ float g_Pf[Dd * HALL];
__device__ float g_zbias[Dd];
__device__ __nv_bfloat16 g_B2h[N2 * K2];
__device__ __nv_bfloat16 g_B2l[N2 * K2];
__device__ float g_bias2[N2];

// smem layout (bytes)
#define ROWB  2128                 // 532 floats per C1 row
#define OFF_C1 0
#define OFF_BH (TM * ROWB)         // 136192
#define OFF_BL (OFF_BH + N2 * 40)  // +11520
#define OFF_AH (OFF_BL + N2 * 40)
#define OFF_AL (OFF_AH + TM * 40)
#define OFF_U  (OFF_AL + TM * 40)
#define SMEM_TOTAL (OFF_U + TM * UD * 4)   // 168448

__device__ __forceinline__ void split_bf16(float v, __nv_bfloat16& hi, __nv_bfloat16& lo) {
    hi = __float2bfloat16(v);
    lo = __float2bfloat16(v - __bfloat162float(hi));
}

__device__ __forceinline__ void mma_bf16(float* d, const unsigned* a, const unsigned* b) {
    asm volatile(
        "mma.sync.aligned.m16n8k16.row.col.f32.bf16.bf16.f32 "
        "{%0,%1,%2,%3},{%4,%5,%6,%7},{%8,%9},{%0,%1,%2,%3};\n"
        : "+f"(d[0]), "+f"(d[1]), "+f"(d[2]), "+f"(d[3])
        : "r"(a[0]), "r"(a[1]), "r"(a[2]), "r"(a[3]), "r"(b[0]), "r"(b[1]));
}

// ======================= precompute kernels =======================
__global__ void pre_w1(const float* __restrict__ W1, const float* __restrict__ gates) {
    int e = blockIdx.x * 256 + threadIdx.x;
    if (e >= HALL * MEAS) return;
    int row = e / MEAS, k = e % MEAS;
    int n = row >> 7;
    float scale = 1.f;
    if (k < Dd) scale = 1.f / (1.f + expf(-gates[n * Dd + k]));
    split_bf16(W1[e] * scale, g_W1h[e], g_W1l[e]);
}

__global__ void pre_M_Mu(const float* __restrict__ Wout, const float* __restrict__ Bmat) {
    int e = blockIdx.x * 256 + threadIdx.x;
    if (e < NBR * Dd * RH) {
        int n = e / (Dd * RH);
        int rem = e % (Dd * RH);
        int d = rem / RH, j = rem % RH;
        const float* wr = Wout + (n * Dd + d) * RH;
        const float* br = Bmat + n * RH * (RH + UD) + j;
        float s = 0.f;
        #pragma unroll 8
        for (int r = 0; r < RH; r++) s += wr[r] * br[r * (RH + UD)];
        g_M[e] = s;
    } else {
        int e2 = e - NBR * Dd * RH;
        if (e2 < Dd * UD) {
            int d = e2 / UD, u = e2 % UD;
            float s = 0.f;
            for (int n = 0; n < NBR; n++) {
                const float* wr = Wout + (n * Dd + d) * RH;
                const float* br = Bmat + n * RH * (RH + UD) + RH + u;
                #pragma unroll 8
                for (int r = 0; r < RH; r++) s += wr[r] * br[r * (RH + UD)];
            }
            g_Mu[e2] = s;
        }
    }
}

__global__ void pre_P(const float* __restrict__ W2, const float* __restrict__ b2) {
    int e = blockIdx.x * 256 + threadIdx.x;
    if (e < NBR * Dd * MH) {
        int n = e / (Dd * MH);
        int rem = e % (Dd * MH);
        int d = rem / MH, h = rem % MH;
        const float* m = g_M + (n * Dd + d) * RH;
        const float* w = W2 + n * RH * MH + h;
        float s = 0.f;
        #pragma unroll 8
        for (int j = 0; j < RH; j++) s += m[j] * w[j * MH];
        g_Pf[d * HALL + n * MH + h] = s;
    } else if (e < NBR * Dd * MH + Dd) {
        int d = e - NBR * Dd * MH;
        float s = 0.f;
        for (int n = 0; n < NBR; n++) {
            const float* m = g_M + (n * Dd + d) * RH;
            const float* bb = b2 + n * RH;
            #pragma unroll 8
            for (int j = 0; j < RH; j++) s += m[j] * bb[j];
        }
        g_zbias[d] = s;
    }
}

__global__ void pre_B2(const float* __restrict__ C, const float* __restrict__ Dm) {
    int e = blockIdx.x * 256 + threadIdx.x;
    if (e >= N2 * K2) return;
    int n = e / K2, k = e % K2;
    float val = 0.f;
    if (n < Dd) {
        val = (k < HALL) ? g_Pf[n * HALL + k] : g_Mu[n * UD + (k - HALL)];
    } else if (n < Dd + NOBS) {
        int o = n - Dd;
        if (k < HALL) {
            float s = 0.f;
            #pragma unroll 8
            for (int d = 0; d < Dd; d++) s += C[o * Dd + d] * g_Pf[d * HALL + k];
            val = s;
        } else {
            int u = k - HALL;
            float s = Dm[o * UD + u];
            #pragma unroll 8
            for (int d = 0; d < Dd; d++) s += C[o * Dd + d] * g_Mu[d * UD + u];
            val = s;
        }
    }
    split_bf16(val, g_B2h[e], g_B2l[e]);
    if (k == 0) {
        float bv = 0.f;
        if (n < Dd) bv = g_zbias[n];
        else if (n < Dd + NOBS) {
            int o = n - Dd;
            float s = 0.f;
            #pragma unroll 8
            for (int d = 0; d < Dd; d++) s += C[o * Dd + d] * g_zbias[d];
            bv = s;
        }
        g_bias2[n] = bv;
    }
}

// ======================= main fused kernel =======================
__global__ __launch_bounds__(256, 1) void skolr_mma(
    const float* __restrict__ z_dyn, const float* __restrict__ z_static,
    const float* __restrict__ dtp,   const float* __restrict__ ut,
    const float* __restrict__ b1g,   const float* __restrict__ gammag,
    const float* __restrict__ betag, float* __restrict__ out)
{
    extern __shared__ char sm[];
    float* c1 = (float*)sm;                                  // [64][532] fp32, later hi/lo planes per row
    __nv_bfloat16* s_bh = (__nv_bfloat16*)(sm + OFF_BH);     // [288][20]
    __nv_bfloat16* s_bl = (__nv_bfloat16*)(sm + OFF_BL);
    __nv_bfloat16* s_ah = (__nv_bfloat16*)(sm + OFF_AH);     // [64][20]
    __nv_bfloat16* s_al = (__nv_bfloat16*)(sm + OFF_AL);
    float* s_u = (float*)(sm + OFF_U);                       // [64][16]

    const int tid = threadIdx.x;
    const int w = tid >> 5, lane = tid & 31;
    const int wm = w >> 1, wn = w & 1;
    const int g = lane >> 2, t4 = lane & 3;
    const int row0 = blockIdx.x * TM;
    const float dt = dtp[0];

    // stage u*dt
    for (int idx = tid; idx < TM * UD; idx += 256)
        s_u[idx] = ut[(size_t)(row0 + (idx >> 4)) * UD + (idx & 15)] * dt;

    // =============== GEMM1: C1[64][512] = X[64][320] * W1eff^T ===============
    for (int p = 0; p < 2; p++) {
        const int np0 = p * 256;
        float acc[16][4];
        #pragma unroll
        for (int i = 0; i < 16; i++)
            #pragma unroll
            for (int j = 0; j < 4; j++) acc[i][j] = 0.f;

        for (int kc = 0; kc < 20; kc++) {
            const int k0 = kc * 16;
            __syncthreads();
            // stage A chunk [64][16] split hi/lo
            #pragma unroll
            for (int idx = tid; idx < TM * 16; idx += 256) {
                int m = idx >> 4, k = idx & 15, gk = k0 + k;
                float v = (gk < Dd) ? z_dyn[(size_t)(row0 + m) * Dd + gk]
                                    : z_static[(size_t)(row0 + m) * SDIM + gk - Dd];
                __nv_bfloat16 hi, lo; split_bf16(v, hi, lo);
                s_ah[m * 20 + k] = hi; s_al[m * 20 + k] = lo;
            }
            // stage B chunk [256][16] from precomputed planes
            #pragma unroll
            for (int idx = tid; idx < 256 * 4; idx += 256) {
                int n = idx >> 2, j = idx & 3;
                *(uint2*)&s_bh[n * 20 + j * 4] = *(const uint2*)&g_W1h[(size_t)(np0 + n) * MEAS + k0 + j * 4];
                *(uint2*)&s_bl[n * 20 + j * 4] = *(const uint2*)&g_W1l[(size_t)(np0 + n) * MEAS + k0 + j * 4];
            }
            __syncthreads();

            const int ar = wm * 16 + g;
            unsigned ah[4], al[4];
            ah[0] = *(const unsigned*)(s_ah + ar * 20 + t4 * 2);
            ah[1] = *(const unsigned*)(s_ah + (ar + 8) * 20 + t4 * 2);
            ah[2] = *(const unsigned*)(s_ah + ar * 20 + t4 * 2 + 8);
            ah[3] = *(const unsigned*)(s_ah + (ar + 8) * 20 + t4 * 2 + 8);
            al[0] = *(const unsigned*)(s_al + ar * 20 + t4 * 2);
            al[1] = *(const unsigned*)(s_al + (ar + 8) * 20 + t4 * 2);
            al[2] = *(const unsigned*)(s_al + ar * 20 + t4 * 2 + 8);
            al[3] = *(const unsigned*)(s_al + (ar + 8) * 20 + t4 * 2 + 8);

            #pragma unroll
            for (int nt = 0; nt < 16; nt++) {
                const int br = wn * 128 + nt * 8 + g;
                unsigned bh[2], bl[2];
                bh[0] = *(const unsigned*)(s_bh + br * 20 + t4 * 2);
                bh[1] = *(const unsigned*)(s_bh + br * 20 + t4 * 2 + 8);
                bl[0] = *(const unsigned*)(s_bl + br * 20 + t4 * 2);
                bl[1] = *(const unsigned*)(s_bl + br * 20 + t4 * 2 + 8);
                mma_bf16(acc[nt], ah, bh);
                mma_bf16(acc[nt], ah, bl);
                mma_bf16(acc[nt], al, bh);
            }
        }
        // epilogue: +b1 -> fp32 C1
        #pragma unroll
        for (int nt = 0; nt < 16; nt++) {
            const int n0 = np0 + wn * 128 + nt * 8 + t4 * 2;
            const float b1a = __ldg(&b1g[n0]), b1b = __ldg(&b1g[n0 + 1]);
            float* c = c1 + (wm * 16 + g) * 532 + n0;
            c[0] = acc[nt][0] + b1a; c[1] = acc[nt][1] + b1b;
            c += 8 * 532;
            c[0] = acc[nt][2] + b1a; c[1] = acc[nt][3] + b1b;
        }
    }
    __syncthreads();

    // =============== per-branch LN(128) + exact GELU + repack hi/lo + append u ===============
    for (int rr = 0; rr < 8; rr++) {
        const int r = w * 8 + rr;
        const float* crow = c1 + r * 532;
        float v[16];
        #pragma unroll
        for (int j = 0; j < 16; j++) v[j] = crow[lane + 32 * j];
        float o[16];
        #pragma unroll
        for (int br = 0; br < 4; br++) {
            float s = 0.f, ss = 0.f;
            #pragma unroll
            for (int j = br * 4; j < br * 4 + 4; j++) { s += v[j]; ss = fmaf(v[j], v[j], ss); }
            #pragma unroll
            for (int off = 16; off > 0; off >>= 1) {
                s  += __shfl_xor_sync(0xffffffffu, s, off);
                ss += __shfl_xor_sync(0xffffffffu, ss, off);
            }
            const float mean = s * (1.f / 128.f);
            const float var  = ss * (1.f / 128.f) - mean * mean;
            const float inv  = rsqrtf(var + 1e-5f);
            #pragma unroll
            for (int j = br * 4; j < br * 4 + 4; j++) {
                const int col = lane + 32 * j;
                float t = (v[j] - mean) * inv * __ldg(&gammag[col]) + __ldg(&betag[col]);
                o[j] = 0.5f * t * (1.f + erff(t * 0.70710678118654752f));
            }
        }
        __syncwarp();
        char* rb = sm + r * ROWB;
        #pragma unroll
        for (int j = 0; j < 16; j++) {
            const int col = lane + 32 * j;
            __nv_bfloat16 hi, lo; split_bf16(o[j], hi, lo);
            *(__nv_bfloat16*)(rb + col * 2) = hi;
            *(__nv_bfloat16*)(rb + 1064 + col * 2) = lo;
        }
        if (lane < UD) {
            __nv_bfloat16 hi, lo; split_bf16(s_u[r * UD + lane], hi, lo);
            *(__nv_bfloat16*)(rb + (HALL + lane) * 2) = hi;
            *(__nv_bfloat16*)(rb + 1064 + (HALL + lane) * 2) = lo;
        }
    }
    __syncthreads();

    // =============== GEMM2: [64][288] = H'[64][528] * B2^T  (z_next + yt fused) ===============
    float acc2[18][4];
    #pragma unroll
    for (int i = 0; i < 18; i++)
        #pragma unroll
        for (int j = 0; j < 4; j++) acc2[i][j] = 0.f;

    for (int kc = 0; kc < 33; kc++) {
        const int k0 = kc * 16;
        __syncthreads();
        for (int idx = tid; idx < N2 * 4; idx += 256) {
            int n = idx >> 2, j = idx & 3;
            *(uint2*)&s_bh[n * 20 + j * 4] = *(const uint2*)&g_B2h[(size_t)n * K2 + k0 + j * 4];
            *(uint2*)&s_bl[n * 20 + j * 4] = *(const uint2*)&g_B2l[(size_t)n * K2 + k0 + j * 4];
        }
        __syncthreads();

        const int ar = wm * 16 + g;
        const char* ra = sm + ar * ROWB;
        const char* rb2 = sm + (ar + 8) * ROWB;
        const int kb = (k0 + t4 * 2) * 2;
        unsigned ah[4], al[4];
        ah[0] = *(const unsigned*)(ra + kb);
        ah[1] = *(const unsigned*)(rb2 + kb);
        ah[2] = *(const unsigned*)(ra + kb + 16);
        ah[3] = *(const unsigned*)(rb2 + kb + 16);
        al[0] = *(const unsigned*)(ra + 1064 + kb);
        al[1] = *(const unsigned*)(rb2 + 1064 + kb);
        al[2] = *(const unsigned*)(ra + 1064 + kb + 16);
        al[3] = *(const unsigned*)(rb2 + 1064 + kb + 16);

        #pragma unroll
        for (int nt = 0; nt < 18; nt++) {
            const int br = wn * 144 + nt * 8 + g;
            unsigned bh[2], bl[2];
            bh[0] = *(const unsigned*)(s_bh + br * 20 + t4 * 2);
            bh[1] = *(const unsigned*)(s_bh + br * 20 + t4 * 2 + 8);
            bl[0] = *(const unsigned*)(s_bl + br * 20 + t4 * 2);
            bl[1] = *(const unsigned*)(s_bl + br * 20 + t4 * 2 + 8);
            mma_bf16(acc2[nt], ah, bh);
            mma_bf16(acc2[nt], ah, bl);
            mma_bf16(acc2[nt], al, bh);
        }
    }

    // epilogue: + bias2, write z_next and yt
    float* out_yt = out + (size_t)BSZ * Dd;
    #pragma unroll
    for (int nt = 0; nt < 18; nt++) {
        const int n0 = wn * 144 + nt * 8 + t4 * 2;
        const float ba = __ldg(&g_bias2[n0]), bb = __ldg(&g_bias2[n0 + 1]);
        const int r = wm * 16 + g;
        float v0 = acc2[nt][0] + ba, v1 = acc2[nt][1] + bb;
        float v2 = acc2[nt][2] + ba, v3 = acc2[nt][3] + bb;
        if (n0 < Dd) {
            *(float2*)&out[(size_t)(row0 + r) * Dd + n0]     = make_float2(v0, v1);
            *(float2*)&out[(size_t)(row0 + r + 8) * Dd + n0] = make_float2(v2, v3);
        } else {
            const int o = n0 - Dd;
            if (o < NOBS)     { out_yt[(size_t)(row0 + r) * NOBS + o]     = v0;
                                out_yt[(size_t)(row0 + r + 8) * NOBS + o] = v2; }
            if (o + 1 < NOBS) { out_yt[(size_t)(row0 + r) * NOBS + o + 1]     = v1;
                                out_yt[(size_t)(row0 + r + 8) * NOBS + o + 1] = v3; }
        }
    }
}

extern "C" void kernel_launch(void* const* d_in, const int* in_sizes, int n_in,
                              void* d_out, int out_size) {
    const float* z_dyn    = (const float*)d_in[0];
    const float* z_static = (const float*)d_in[1];
    const float* dt       = (const float*)d_in[2];
    const float* ut       = (const float*)d_in[3];
    const float* gates    = (const float*)d_in[4];
    const float* W1       = (const float*)d_in[5];
    const float* b1       = (const float*)d_in[6];
    const float* gamma    = (const float*)d_in[7];
    const float* beta     = (const float*)d_in[8];
    const float* W2       = (const float*)d_in[9];
    const float* b2       = (const float*)d_in[10];
    const float* Bmat     = (const float*)d_in[13];
    const float* Wout     = (const float*)d_in[14];
    const float* Cmat     = (const float*)d_in[15];
    const float* Dm       = (const float*)d_in[16];
    float* out = (float*)d_out;

    pre_w1<<<(HALL * MEAS + 255) / 256, 256>>>(W1, gates);
    pre_M_Mu<<<(NBR * Dd * RH + Dd * UD + 255) / 256, 256>>>(Wout, Bmat);
    pre_P<<<(NBR * Dd * MH + Dd + 255) / 256, 256>>>(W2, b2);
    pre_B2<<<(N2 * K2 + 255) / 256, 256>>>(Cmat, Dm);

    cudaFuncSetAttribute(skolr_mma, cudaFuncAttributeMaxDynamicSharedMemorySize, SMEM_TOTAL);
    skolr_mma<<<BSZ / TM, 256, SMEM_TOTAL>>>(z_dyn, z_static, dt, ut, b1, gamma, beta, out);
}

// round 3
// speedup vs baseline: 2.1262x; 1.0121x over previous
#include <cuda_runtime.h>
#include <cuda_bf16.h>
#include <math.h>

#define NBR   4
#define Dd    256
#define SDIM  64
#define MEAS  320
#define MH    128
#define RH    64
#define UD    16
#define NOBS  25
#define BSZ   32768
#define HALL  512          // NBR*MH
#define K2    528          // HALL + UD
#define N2    288          // Dd + 32 (25 yt cols padded)
#define TM    64           // rows per CTA

// ---- device scratch (recomputed every launch; no allocs) ----
__device__ __nv_bfloat16 g_W1h[HALL * MEAS];
__device__ __nv_bfloat16 g_W1l[HALL * MEAS];
__device__ float g_M[NBR * Dd * RH];
__device__ float g_Mu[Dd * UD];
__device__ float g_Pf[Dd * HALL];
__device__ float g_zbias[Dd];
__device__ __nv_bfloat16 g_B2h[N2 * K2];
__device__ __nv_bfloat16 g_B2l[N2 * K2];
__device__ float g_bias2[N2];

// smem layout (bytes)
#define ROWB  2128                 // 532 floats per C1 row
#define OFF_C1 0
#define OFF_BH (TM * ROWB)         // 136192
#define OFF_BL (OFF_BH + N2 * 40)  // +11520
#define OFF_AH (OFF_BL + N2 * 40)
#define OFF_AL (OFF_AH + TM * 40)
#define OFF_U  (OFF_AL + TM * 40)
#define SMEM_TOTAL (OFF_U + TM * UD * 4)   // 168448

__device__ __forceinline__ void split_bf16(float v, __nv_bfloat16& hi, __nv_bfloat16& lo) {
    hi = __float2bfloat16(v);
    lo = __float2bfloat16(v - __bfloat162float(hi));
}

__device__ __forceinline__ void mma_bf16(float* d, const unsigned* a, const unsigned* b) {
    asm volatile(
        "mma.sync.aligned.m16n8k16.row.col.f32.bf16.bf16.f32 "
        "{%0,%1,%2,%3},{%4,%5,%6,%7},{%8,%9},{%0,%1,%2,%3};\n"
        : "+f"(d[0]), "+f"(d[1]), "+f"(d[2]), "+f"(d[3])
        : "r"(a[0]), "r"(a[1]), "r"(a[2]), "r"(a[3]), "r"(b[0]), "r"(b[1]));
}

// ======================= precompute kernels =======================
__global__ void pre_w1(const float* __restrict__ W1, const float* __restrict__ gates) {
    int e = blockIdx.x * 256 + threadIdx.x;
    if (e >= HALL * MEAS) return;
    int row = e / MEAS, k = e % MEAS;
    int n = row >> 7;
    float scale = 1.f;
    if (k < Dd) scale = 1.f / (1.f + expf(-gates[n * Dd + k]));
    split_bf16(W1[e] * scale, g_W1h[e], g_W1l[e]);
}

__global__ void pre_M_Mu(const float* __restrict__ Wout, const float* __restrict__ Bmat) {
    int e = blockIdx.x * 256 + threadIdx.x;
    if (e < NBR * Dd * RH) {
        int n = e / (Dd * RH);
        int rem = e % (Dd * RH);
        int d = rem / RH, j = rem % RH;
        const float* wr = Wout + (n * Dd + d) * RH;
        const float* br = Bmat + n * RH * (RH + UD) + j;
        float s = 0.f;
        #pragma unroll 8
        for (int r = 0; r < RH; r++) s += wr[r] * br[r * (RH + UD)];
        g_M[e] = s;
    } else {
        int e2 = e - NBR * Dd * RH;
        if (e2 < Dd * UD) {
            int d = e2 / UD, u = e2 % UD;
            float s = 0.f;
            for (int n = 0; n < NBR; n++) {
                const float* wr = Wout + (n * Dd + d) * RH;
                const float* br = Bmat + n * RH * (RH + UD) + RH + u;
                #pragma unroll 8
                for (int r = 0; r < RH; r++) s += wr[r] * br[r * (RH + UD)];
            }
            g_Mu[e2] = s;
        }
    }
}

__global__ void pre_P(const float* __restrict__ W2, const float* __restrict__ b2) {
    int e = blockIdx.x * 256 + threadIdx.x;
    if (e < NBR * Dd * MH) {
        int n = e / (Dd * MH);
        int rem = e % (Dd * MH);
        int d = rem / MH, h = rem % MH;
        const float* m = g_M + (n * Dd + d) * RH;
        const float* w = W2 + n * RH * MH + h;
        float s = 0.f;
        #pragma unroll 8
        for (int j = 0; j < RH; j++) s += m[j] * w[j * MH];
        g_Pf[d * HALL + n * MH + h] = s;
    } else if (e < NBR * Dd * MH + Dd) {
        int d = e - NBR * Dd * MH;
        float s = 0.f;
        for (int n = 0; n < NBR; n++) {
            const float* m = g_M + (n * Dd + d) * RH;
            const float* bb = b2 + n * RH;
            #pragma unroll 8
            for (int j = 0; j < RH; j++) s += m[j] * bb[j];
        }
        g_zbias[d] = s;
    }
}

__global__ void pre_B2(const float* __restrict__ C, const float* __restrict__ Dm) {
    int e = blockIdx.x * 256 + threadIdx.x;
    if (e >= N2 * K2) return;
    int n = e / K2, k = e % K2;
    float val = 0.f;
    if (n < Dd) {
        val = (k < HALL) ? g_Pf[n * HALL + k] : g_Mu[n * UD + (k - HALL)];
    } else if (n < Dd + NOBS) {
        int o = n - Dd;
        if (k < HALL) {
            float s = 0.f;
            #pragma unroll 8
            for (int d = 0; d < Dd; d++) s += C[o * Dd + d] * g_Pf[d * HALL + k];
            val = s;
        } else {
            int u = k - HALL;
            float s = Dm[o * UD + u];
            #pragma unroll 8
            for (int d = 0; d < Dd; d++) s += C[o * Dd + d] * g_Mu[d * UD + u];
            val = s;
        }
    }
    split_bf16(val, g_B2h[e], g_B2l[e]);
    if (k == 0) {
        float bv = 0.f;
        if (n < Dd) bv = g_zbias[n];
        else if (n < Dd + NOBS) {
            int o = n - Dd;
            float s = 0.f;
            #pragma unroll 8
            for (int d = 0; d < Dd; d++) s += C[o * Dd + d] * g_zbias[d];
            bv = s;
        }
        g_bias2[n] = bv;
    }
}

// ======================= main fused kernel =======================
__global__ __launch_bounds__(256, 1) void skolr_mma(
    const float* __restrict__ z_dyn, const float* __restrict__ z_static,
    const float* __restrict__ dtp,   const float* __restrict__ ut,
    const float* __restrict__ b1g,   const float* __restrict__ gammag,
    const float* __restrict__ betag, float* __restrict__ out)
{
    extern __shared__ char sm[];
    float* c1 = (float*)sm;                                  // [64][532] fp32, later hi/lo planes per row
    __nv_bfloat16* s_bh = (__nv_bfloat16*)(sm + OFF_BH);     // [288][20]
    __nv_bfloat16* s_bl = (__nv_bfloat16*)(sm + OFF_BL);
    __nv_bfloat16* s_ah = (__nv_bfloat16*)(sm + OFF_AH);     // [64][20]
    __nv_bfloat16* s_al = (__nv_bfloat16*)(sm + OFF_AL);
    float* s_u = (float*)(sm + OFF_U);                       // [64][16]

    const int tid = threadIdx.x;
    const int w = tid >> 5, lane = tid & 31;
    const int wm = w >> 1, wn = w & 1;
    const int g = lane >> 2, t4 = lane & 3;
    const int row0 = blockIdx.x * TM;
    const float dt = dtp[0];

    // stage u*dt
    for (int idx = tid; idx < TM * UD; idx += 256)
        s_u[idx] = ut[(size_t)(row0 + (idx >> 4)) * UD + (idx & 15)] * dt;

    // =============== GEMM1: C1[64][512] = X[64][320] * W1eff^T ===============
    for (int p = 0; p < 2; p++) {
        const int np0 = p * 256;
        float acc[16][4];
        #pragma unroll
        for (int i = 0; i < 16; i++)
            #pragma unroll
            for (int j = 0; j < 4; j++) acc[i][j] = 0.f;

        for (int kc = 0; kc < 20; kc++) {
            const int k0 = kc * 16;
            __syncthreads();
            // stage A chunk [64][16] split hi/lo
            #pragma unroll
            for (int idx = tid; idx < TM * 16; idx += 256) {
                int m = idx >> 4, k = idx & 15, gk = k0 + k;
                float v = (gk < Dd) ? z_dyn[(size_t)(row0 + m) * Dd + gk]
                                    : z_static[(size_t)(row0 + m) * SDIM + gk - Dd];
                __nv_bfloat16 hi, lo; split_bf16(v, hi, lo);
                s_ah[m * 20 + k] = hi; s_al[m * 20 + k] = lo;
            }
            // stage B chunk [256][16] from precomputed planes
            #pragma unroll
            for (int idx = tid; idx < 256 * 4; idx += 256) {
                int n = idx >> 2, j = idx & 3;
                *(uint2*)&s_bh[n * 20 + j * 4] = *(const uint2*)&g_W1h[(size_t)(np0 + n) * MEAS + k0 + j * 4];
                *(uint2*)&s_bl[n * 20 + j * 4] = *(const uint2*)&g_W1l[(size_t)(np0 + n) * MEAS + k0 + j * 4];
            }
            __syncthreads();

            const int ar = wm * 16 + g;
            unsigned ah[4], al[4];
            ah[0] = *(const unsigned*)(s_ah + ar * 20 + t4 * 2);
            ah[1] = *(const unsigned*)(s_ah + (ar + 8) * 20 + t4 * 2);
            ah[2] = *(const unsigned*)(s_ah + ar * 20 + t4 * 2 + 8);
            ah[3] = *(const unsigned*)(s_ah + (ar + 8) * 20 + t4 * 2 + 8);
            al[0] = *(const unsigned*)(s_al + ar * 20 + t4 * 2);
            al[1] = *(const unsigned*)(s_al + (ar + 8) * 20 + t4 * 2);
            al[2] = *(const unsigned*)(s_al + ar * 20 + t4 * 2 + 8);
            al[3] = *(const unsigned*)(s_al + (ar + 8) * 20 + t4 * 2 + 8);

            #pragma unroll
            for (int nt = 0; nt < 16; nt++) {
                const int br = wn * 128 + nt * 8 + g;
                unsigned bh[2], bl[2];
                bh[0] = *(const unsigned*)(s_bh + br * 20 + t4 * 2);
                bh[1] = *(const unsigned*)(s_bh + br * 20 + t4 * 2 + 8);
                bl[0] = *(const unsigned*)(s_bl + br * 20 + t4 * 2);
                bl[1] = *(const unsigned*)(s_bl + br * 20 + t4 * 2 + 8);
                mma_bf16(acc[nt], ah, bh);
                mma_bf16(acc[nt], ah, bl);
                mma_bf16(acc[nt], al, bh);
            }
        }
        // epilogue: +b1 -> fp32 C1
        #pragma unroll
        for (int nt = 0; nt < 16; nt++) {
            const int n0 = np0 + wn * 128 + nt * 8 + t4 * 2;
            const float b1a = __ldg(&b1g[n0]), b1b = __ldg(&b1g[n0 + 1]);
            float* c = c1 + (wm * 16 + g) * 532 + n0;
            c[0] = acc[nt][0] + b1a; c[1] = acc[nt][1] + b1b;
            c += 8 * 532;
            c[0] = acc[nt][2] + b1a; c[1] = acc[nt][3] + b1b;
        }
    }
    __syncthreads();

    // =============== per-branch LN(128) + exact GELU + repack hi/lo + append u ===============
    for (int rr = 0; rr < 8; rr++) {
        const int r = w * 8 + rr;
        const float* crow = c1 + r * 532;
        float v[16];
        #pragma unroll
        for (int j = 0; j < 16; j++) v[j] = crow[lane + 32 * j];
        float o[16];
        #pragma unroll
        for (int br = 0; br < 4; br++) {
            float s = 0.f, ss = 0.f;
            #pragma unroll
            for (int j = br * 4; j < br * 4 + 4; j++) { s += v[j]; ss = fmaf(v[j], v[j], ss); }
            #pragma unroll
            for (int off = 16; off > 0; off >>= 1) {
                s  += __shfl_xor_sync(0xffffffffu, s, off);
                ss += __shfl_xor_sync(0xffffffffu, ss, off);
            }
            const float mean = s * (1.f / 128.f);
            const float var  = ss * (1.f / 128.f) - mean * mean;
            const float inv  = rsqrtf(var + 1e-5f);
            #pragma unroll
            for (int j = br * 4; j < br * 4 + 4; j++) {
                const int col = lane + 32 * j;
                float t = (v[j] - mean) * inv * __ldg(&gammag[col]) + __ldg(&betag[col]);
                o[j] = 0.5f * t * (1.f + erff(t * 0.70710678118654752f));
            }
        }
        __syncwarp();
        char* rb = sm + r * ROWB;
        #pragma unroll
        for (int j = 0; j < 16; j++) {
            const int col = lane + 32 * j;
            __nv_bfloat16 hi, lo; split_bf16(o[j], hi, lo);
            *(__nv_bfloat16*)(rb + col * 2) = hi;
            *(__nv_bfloat16*)(rb + 1064 + col * 2) = lo;
        }
        if (lane < UD) {
            __nv_bfloat16 hi, lo; split_bf16(s_u[r * UD + lane], hi, lo);
            *(__nv_bfloat16*)(rb + (HALL + lane) * 2) = hi;
            *(__nv_bfloat16*)(rb + 1064 + (HALL + lane) * 2) = lo;
        }
    }
    __syncthreads();

    // =============== GEMM2: [64][288] = H'[64][528] * B2^T  (z_next + yt fused) ===============
    float acc2[18][4];
    #pragma unroll
    for (int i = 0; i < 18; i++)
        #pragma unroll
        for (int j = 0; j < 4; j++) acc2[i][j] = 0.f;

    for (int kc = 0; kc < 33; kc++) {
        const int k0 = kc * 16;
        __syncthreads();
        for (int idx = tid; idx < N2 * 4; idx += 256) {
            int n = idx >> 2, j = idx & 3;
            *(uint2*)&s_bh[n * 20 + j * 4] = *(const uint2*)&g_B2h[(size_t)n * K2 + k0 + j * 4];
            *(uint2*)&s_bl[n * 20 + j * 4] = *(const uint2*)&g_B2l[(size_t)n * K2 + k0 + j * 4];
        }
        __syncthreads();

        const int ar = wm * 16 + g;
        const char* ra = sm + ar * ROWB;
        const char* rb2 = sm + (ar + 8) * ROWB;
        const int kb = (k0 + t4 * 2) * 2;
        unsigned ah[4], al[4];
        ah[0] = *(const unsigned*)(ra + kb);
        ah[1] = *(const unsigned*)(rb2 + kb);
        ah[2] = *(const unsigned*)(ra + kb + 16);
        ah[3] = *(const unsigned*)(rb2 + kb + 16);
        al[0] = *(const unsigned*)(ra + 1064 + kb);
        al[1] = *(const unsigned*)(rb2 + 1064 + kb);
        al[2] = *(const unsigned*)(ra + 1064 + kb + 16);
        al[3] = *(const unsigned*)(rb2 + 1064 + kb + 16);

        #pragma unroll
        for (int nt = 0; nt < 18; nt++) {
            const int br = wn * 144 + nt * 8 + g;
            unsigned bh[2], bl[2];
            bh[0] = *(const unsigned*)(s_bh + br * 20 + t4 * 2);
            bh[1] = *(const unsigned*)(s_bh + br * 20 + t4 * 2 + 8);
            bl[0] = *(const unsigned*)(s_bl + br * 20 + t4 * 2);
            bl[1] = *(const unsigned*)(s_bl + br * 20 + t4 * 2 + 8);
            mma_bf16(acc2[nt], ah, bh);
            mma_bf16(acc2[nt], ah, bl);
            mma_bf16(acc2[nt], al, bh);
        }
    }

    // epilogue: + bias2, write z_next and yt
    float* out_yt = out + (size_t)BSZ * Dd;
    #pragma unroll
    for (int nt = 0; nt < 18; nt++) {
        const int n0 = wn * 144 + nt * 8 + t4 * 2;
        const float ba = __ldg(&g_bias2[n0]), bb = __ldg(&g_bias2[n0 + 1]);
        const int r = wm * 16 + g;
        float v0 = acc2[nt][0] + ba, v1 = acc2[nt][1] + bb;
        float v2 = acc2[nt][2] + ba, v3 = acc2[nt][3] + bb;
        if (n0 < Dd) {
            *(float2*)&out[(size_t)(row0 + r) * Dd + n0]     = make_float2(v0, v1);
            *(float2*)&out[(size_t)(row0 + r + 8) * Dd + n0] = make_float2(v2, v3);
        } else {
            const int o = n0 - Dd;
            if (o < NOBS)     { out_yt[(size_t)(row0 + r) * NOBS + o]     = v0;
                                out_yt[(size_t)(row0 + r + 8) * NOBS + o] = v2; }
            if (o + 1 < NOBS) { out_yt[(size_t)(row0 + r) * NOBS + o + 1]     = v1;
                                out_yt[(size_t)(row0 + r + 8) * NOBS + o + 1] = v3; }
        }
    }
}

extern "C" void kernel_launch(void* const* d_in, const int* in_sizes, int n_in,
                              void* d_out, int out_size) {
    const float* z_dyn    = (const float*)d_in[0];
    const float* z_static = (const float*)d_in[1];
    const float* dt       = (const float*)d_in[2];
    const float* ut       = (const float*)d_in[3];
    const float* gates    = (const float*)d_in[4];
    const float* W1       = (const float*)d_in[5];
    const float* b1       = (const float*)d_in[6];
    const float* gamma    = (const float*)d_in[7];
    const float* beta     = (const float*)d_in[8];
    const float* W2       = (const float*)d_in[9];
    const float* b2       = (const float*)d_in[10];
    const float* Bmat     = (const float*)d_in[13];
    const float* Wout     = (const float*)d_in[14];
    const float* Cmat     = (const float*)d_in[15];
    const float* Dm       = (const float*)d_in[16];
    float* out = (float*)d_out;

    pre_w1<<<(HALL * MEAS + 255) / 256, 256>>>(W1, gates);
    pre_M_Mu<<<(NBR * Dd * RH + Dd * UD + 255) / 256, 256>>>(Wout, Bmat);
    pre_P<<<(NBR * Dd * MH + Dd + 255) / 256, 256>>>(W2, b2);
    pre_B2<<<(N2 * K2 + 255) / 256, 256>>>(Cmat, Dm);

    cudaFuncSetAttribute(skolr_mma, cudaFuncAttributeMaxDynamicSharedMemorySize, SMEM_TOTAL);
    skolr_mma<<<BSZ / TM, 256, SMEM_TOTAL>>>(z_dyn, z_static, dt, ut, b1, gamma, beta, out);
}

// round 4
// speedup vs baseline: 2.1272x; 1.0005x over previous
#include <cuda_runtime.h>
#include <cuda_bf16.h>
#include <math.h>

#define NBR   4
#define Dd    256
#define SDIM  64
#define MEAS  320
#define MH    128
#define RH    64
#define UD    16
#define NOBS  25
#define BSZ   32768
#define HALL  512          // NBR*MH
#define K2    528          // HALL + UD
#define N2    288          // Dd + 32 (25 yt cols padded)
#define TM    64           // rows per CTA

// ---- device scratch (recomputed every launch; no allocs) ----
__device__ __nv_bfloat16 g_W1h[HALL * MEAS];
__device__ __nv_bfloat16 g_W1l[HALL * MEAS];
__device__ float g_M[NBR * Dd * RH];
__device__ float g_Mu[Dd * UD];
__device__ float g_Pf[Dd * HALL];
__device__ float g_zbias[Dd];
__device__ __nv_bfloat16 g_B2h[N2 * K2];
__device__ __nv_bfloat16 g_B2l[N2 * K2];
__device__ float g_bias2[N2];

// smem layout (bytes)
#define ROWB  2128                 // 532 floats per C1 row
#define OFF_C1 0
#define OFF_BH (TM * ROWB)         // 136192
#define OFF_BL (OFF_BH + N2 * 40)  // +11520
#define OFF_AH (OFF_BL + N2 * 40)
#define OFF_AL (OFF_AH + TM * 40)
#define OFF_U  (OFF_AL + TM * 40)
#define SMEM_TOTAL (OFF_U + TM * UD * 4)   // 168448

__device__ __forceinline__ void split_bf16(float v, __nv_bfloat16& hi, __nv_bfloat16& lo) {
    hi = __float2bfloat16(v);
    lo = __float2bfloat16(v - __bfloat162float(hi));
}

__device__ __forceinline__ void mma_bf16(float* d, const unsigned* a, const unsigned* b) {
    asm volatile(
        "mma.sync.aligned.m16n8k16.row.col.f32.bf16.bf16.f32 "
        "{%0,%1,%2,%3},{%4,%5,%6,%7},{%8,%9},{%0,%1,%2,%3};\n"
        : "+f"(d[0]), "+f"(d[1]), "+f"(d[2]), "+f"(d[3])
        : "r"(a[0]), "r"(a[1]), "r"(a[2]), "r"(a[3]), "r"(b[0]), "r"(b[1]));
}

// ======================= precompute kernels =======================
__global__ void pre_w1(const float* __restrict__ W1, const float* __restrict__ gates) {
    int e = blockIdx.x * 256 + threadIdx.x;
    if (e >= HALL * MEAS) return;
    int row = e / MEAS, k = e % MEAS;
    int n = row >> 7;
    float scale = 1.f;
    if (k < Dd) scale = 1.f / (1.f + expf(-gates[n * Dd + k]));
    split_bf16(W1[e] * scale, g_W1h[e], g_W1l[e]);
}

__global__ void pre_M_Mu(const float* __restrict__ Wout, const float* __restrict__ Bmat) {
    int e = blockIdx.x * 256 + threadIdx.x;
    if (e < NBR * Dd * RH) {
        int n = e / (Dd * RH);
        int rem = e % (Dd * RH);
        int d = rem / RH, j = rem % RH;
        const float* wr = Wout + (n * Dd + d) * RH;
        const float* br = Bmat + n * RH * (RH + UD) + j;
        float s = 0.f;
        #pragma unroll 8
        for (int r = 0; r < RH; r++) s += wr[r] * br[r * (RH + UD)];
        g_M[e] = s;
    } else {
        int e2 = e - NBR * Dd * RH;
        if (e2 < Dd * UD) {
            int d = e2 / UD, u = e2 % UD;
            float s = 0.f;
            for (int n = 0; n < NBR; n++) {
                const float* wr = Wout + (n * Dd + d) * RH;
                const float* br = Bmat + n * RH * (RH + UD) + RH + u;
                #pragma unroll 8
                for (int r = 0; r < RH; r++) s += wr[r] * br[r * (RH + UD)];
            }
            g_Mu[e2] = s;
        }
    }
}

__global__ void pre_P(const float* __restrict__ W2, const float* __restrict__ b2) {
    int e = blockIdx.x * 256 + threadIdx.x;
    if (e < NBR * Dd * MH) {
        int n = e / (Dd * MH);
        int rem = e % (Dd * MH);
        int d = rem / MH, h = rem % MH;
        const float* m = g_M + (n * Dd + d) * RH;
        const float* w = W2 + n * RH * MH + h;
        float s = 0.f;
        #pragma unroll 8
        for (int j = 0; j < RH; j++) s += m[j] * w[j * MH];
        g_Pf[d * HALL + n * MH + h] = s;
    } else if (e < NBR * Dd * MH + Dd) {
        int d = e - NBR * Dd * MH;
        float s = 0.f;
        for (int n = 0; n < NBR; n++) {
            const float* m = g_M + (n * Dd + d) * RH;
            const float* bb = b2 + n * RH;
            #pragma unroll 8
            for (int j = 0; j < RH; j++) s += m[j] * bb[j];
        }
        g_zbias[d] = s;
    }
}

__global__ void pre_B2(const float* __restrict__ C, const float* __restrict__ Dm) {
    int e = blockIdx.x * 256 + threadIdx.x;
    if (e >= N2 * K2) return;
    int n = e / K2, k = e % K2;
    float val = 0.f;
    if (n < Dd) {
        val = (k < HALL) ? g_Pf[n * HALL + k] : g_Mu[n * UD + (k - HALL)];
    } else if (n < Dd + NOBS) {
        int o = n - Dd;
        if (k < HALL) {
            float s = 0.f;
            #pragma unroll 8
            for (int d = 0; d < Dd; d++) s += C[o * Dd + d] * g_Pf[d * HALL + k];
            val = s;
        } else {
            int u = k - HALL;
            float s = Dm[o * UD + u];
            #pragma unroll 8
            for (int d = 0; d < Dd; d++) s += C[o * Dd + d] * g_Mu[d * UD + u];
            val = s;
        }
    }
    split_bf16(val, g_B2h[e], g_B2l[e]);
    if (k == 0) {
        float bv = 0.f;
        if (n < Dd) bv = g_zbias[n];
        else if (n < Dd + NOBS) {
            int o = n - Dd;
            float s = 0.f;
            #pragma unroll 8
            for (int d = 0; d < Dd; d++) s += C[o * Dd + d] * g_zbias[d];
            bv = s;
        }
        g_bias2[n] = bv;
    }
}

// ======================= main fused kernel =======================
__global__ __launch_bounds__(256, 1) void skolr_mma(
    const float* __restrict__ z_dyn, const float* __restrict__ z_static,
    const float* __restrict__ dtp,   const float* __restrict__ ut,
    const float* __restrict__ b1g,   const float* __restrict__ gammag,
    const float* __restrict__ betag, float* __restrict__ out)
{
    extern __shared__ char sm[];
    float* c1 = (float*)sm;                                  // [64][532] fp32, later hi/lo planes per row
    __nv_bfloat16* s_bh = (__nv_bfloat16*)(sm + OFF_BH);     // [288][20]
    __nv_bfloat16* s_bl = (__nv_bfloat16*)(sm + OFF_BL);
    __nv_bfloat16* s_ah = (__nv_bfloat16*)(sm + OFF_AH);     // [64][20]
    __nv_bfloat16* s_al = (__nv_bfloat16*)(sm + OFF_AL);
    float* s_u = (float*)(sm + OFF_U);                       // [64][16]

    const int tid = threadIdx.x;
    const int w = tid >> 5, lane = tid & 31;
    const int wm = w >> 1, wn = w & 1;
    const int g = lane >> 2, t4 = lane & 3;
    const int row0 = blockIdx.x * TM;
    const float dt = dtp[0];

    // stage u*dt
    for (int idx = tid; idx < TM * UD; idx += 256)
        s_u[idx] = ut[(size_t)(row0 + (idx >> 4)) * UD + (idx & 15)] * dt;

    // =============== GEMM1: C1[64][512] = X[64][320] * W1eff^T ===============
    for (int p = 0; p < 2; p++) {
        const int np0 = p * 256;
        float acc[16][4];
        #pragma unroll
        for (int i = 0; i < 16; i++)
            #pragma unroll
            for (int j = 0; j < 4; j++) acc[i][j] = 0.f;

        for (int kc = 0; kc < 20; kc++) {
            const int k0 = kc * 16;
            __syncthreads();
            // stage A chunk [64][16] split hi/lo
            #pragma unroll
            for (int idx = tid; idx < TM * 16; idx += 256) {
                int m = idx >> 4, k = idx & 15, gk = k0 + k;
                float v = (gk < Dd) ? z_dyn[(size_t)(row0 + m) * Dd + gk]
                                    : z_static[(size_t)(row0 + m) * SDIM + gk - Dd];
                __nv_bfloat16 hi, lo; split_bf16(v, hi, lo);
                s_ah[m * 20 + k] = hi; s_al[m * 20 + k] = lo;
            }
            // stage B chunk [256][16] from precomputed planes
            #pragma unroll
            for (int idx = tid; idx < 256 * 4; idx += 256) {
                int n = idx >> 2, j = idx & 3;
                *(uint2*)&s_bh[n * 20 + j * 4] = *(const uint2*)&g_W1h[(size_t)(np0 + n) * MEAS + k0 + j * 4];
                *(uint2*)&s_bl[n * 20 + j * 4] = *(const uint2*)&g_W1l[(size_t)(np0 + n) * MEAS + k0 + j * 4];
            }
            __syncthreads();

            const int ar = wm * 16 + g;
            unsigned ah[4], al[4];
            ah[0] = *(const unsigned*)(s_ah + ar * 20 + t4 * 2);
            ah[1] = *(const unsigned*)(s_ah + (ar + 8) * 20 + t4 * 2);
            ah[2] = *(const unsigned*)(s_ah + ar * 20 + t4 * 2 + 8);
            ah[3] = *(const unsigned*)(s_ah + (ar + 8) * 20 + t4 * 2 + 8);
            al[0] = *(const unsigned*)(s_al + ar * 20 + t4 * 2);
            al[1] = *(const unsigned*)(s_al + (ar + 8) * 20 + t4 * 2);
            al[2] = *(const unsigned*)(s_al + ar * 20 + t4 * 2 + 8);
            al[3] = *(const unsigned*)(s_al + (ar + 8) * 20 + t4 * 2 + 8);

            #pragma unroll
            for (int nt = 0; nt < 16; nt++) {
                const int br = wn * 128 + nt * 8 + g;
                unsigned bh[2], bl[2];
                bh[0] = *(const unsigned*)(s_bh + br * 20 + t4 * 2);
                bh[1] = *(const unsigned*)(s_bh + br * 20 + t4 * 2 + 8);
                bl[0] = *(const unsigned*)(s_bl + br * 20 + t4 * 2);
                bl[1] = *(const unsigned*)(s_bl + br * 20 + t4 * 2 + 8);
                mma_bf16(acc[nt], ah, bh);
                mma_bf16(acc[nt], ah, bl);
                mma_bf16(acc[nt], al, bh);
            }
        }
        // epilogue: +b1 -> fp32 C1
        #pragma unroll
        for (int nt = 0; nt < 16; nt++) {
            const int n0 = np0 + wn * 128 + nt * 8 + t4 * 2;
            const float b1a = __ldg(&b1g[n0]), b1b = __ldg(&b1g[n0 + 1]);
            float* c = c1 + (wm * 16 + g) * 532 + n0;
            c[0] = acc[nt][0] + b1a; c[1] = acc[nt][1] + b1b;
            c += 8 * 532;
            c[0] = acc[nt][2] + b1a; c[1] = acc[nt][3] + b1b;
        }
    }
    __syncthreads();

    // =============== per-branch LN(128) + exact GELU + repack hi/lo + append u ===============
    for (int rr = 0; rr < 8; rr++) {
        const int r = w * 8 + rr;
        const float* crow = c1 + r * 532;
        float v[16];
        #pragma unroll
        for (int j = 0; j < 16; j++) v[j] = crow[lane + 32 * j];
        float o[16];
        #pragma unroll
        for (int br = 0; br < 4; br++) {
            float s = 0.f, ss = 0.f;
            #pragma unroll
            for (int j = br * 4; j < br * 4 + 4; j++) { s += v[j]; ss = fmaf(v[j], v[j], ss); }
            #pragma unroll
            for (int off = 16; off > 0; off >>= 1) {
                s  += __shfl_xor_sync(0xffffffffu, s, off);
                ss += __shfl_xor_sync(0xffffffffu, ss, off);
            }
            const float mean = s * (1.f / 128.f);
            const float var  = ss * (1.f / 128.f) - mean * mean;
            const float inv  = rsqrtf(var + 1e-5f);
            #pragma unroll
            for (int j = br * 4; j < br * 4 + 4; j++) {
                const int col = lane + 32 * j;
                float t = (v[j] - mean) * inv * __ldg(&gammag[col]) + __ldg(&betag[col]);
                o[j] = 0.5f * t * (1.f + erff(t * 0.70710678118654752f));
            }
        }
        __syncwarp();
        char* rb = sm + r * ROWB;
        #pragma unroll
        for (int j = 0; j < 16; j++) {
            const int col = lane + 32 * j;
            __nv_bfloat16 hi, lo; split_bf16(o[j], hi, lo);
            *(__nv_bfloat16*)(rb + col * 2) = hi;
            *(__nv_bfloat16*)(rb + 1064 + col * 2) = lo;
        }
        if (lane < UD) {
            __nv_bfloat16 hi, lo; split_bf16(s_u[r * UD + lane], hi, lo);
            *(__nv_bfloat16*)(rb + (HALL + lane) * 2) = hi;
            *(__nv_bfloat16*)(rb + 1064 + (HALL + lane) * 2) = lo;
        }
    }
    __syncthreads();

    // =============== GEMM2: [64][288] = H'[64][528] * B2^T  (z_next + yt fused) ===============
    float acc2[18][4];
    #pragma unroll
    for (int i = 0; i < 18; i++)
        #pragma unroll
        for (int j = 0; j < 4; j++) acc2[i][j] = 0.f;

    for (int kc = 0; kc < 33; kc++) {
        const int k0 = kc * 16;
        __syncthreads();
        for (int idx = tid; idx < N2 * 4; idx += 256) {
            int n = idx >> 2, j = idx & 3;
            *(uint2*)&s_bh[n * 20 + j * 4] = *(const uint2*)&g_B2h[(size_t)n * K2 + k0 + j * 4];
            *(uint2*)&s_bl[n * 20 + j * 4] = *(const uint2*)&g_B2l[(size_t)n * K2 + k0 + j * 4];
        }
        __syncthreads();

        const int ar = wm * 16 + g;
        const char* ra = sm + ar * ROWB;
        const char* rb2 = sm + (ar + 8) * ROWB;
        const int kb = (k0 + t4 * 2) * 2;
        unsigned ah[4], al[4];
        ah[0] = *(const unsigned*)(ra + kb);
        ah[1] = *(const unsigned*)(rb2 + kb);
        ah[2] = *(const unsigned*)(ra + kb + 16);
        ah[3] = *(const unsigned*)(rb2 + kb + 16);
        al[0] = *(const unsigned*)(ra + 1064 + kb);
        al[1] = *(const unsigned*)(rb2 + 1064 + kb);
        al[2] = *(const unsigned*)(ra + 1064 + kb + 16);
        al[3] = *(const unsigned*)(rb2 + 1064 + kb + 16);

        #pragma unroll
        for (int nt = 0; nt < 18; nt++) {
            const int br = wn * 144 + nt * 8 + g;
            unsigned bh[2], bl[2];
            bh[0] = *(const unsigned*)(s_bh + br * 20 + t4 * 2);
            bh[1] = *(const unsigned*)(s_bh + br * 20 + t4 * 2 + 8);
            bl[0] = *(const unsigned*)(s_bl + br * 20 + t4 * 2);
            bl[1] = *(const unsigned*)(s_bl + br * 20 + t4 * 2 + 8);
            mma_bf16(acc2[nt], ah, bh);
            mma_bf16(acc2[nt], ah, bl);
            mma_bf16(acc2[nt], al, bh);
        }
    }

    // epilogue: + bias2, write z_next and yt
    float* out_yt = out + (size_t)BSZ * Dd;
    #pragma unroll
    for (int nt = 0; nt < 18; nt++) {
        const int n0 = wn * 144 + nt * 8 + t4 * 2;
        const float ba = __ldg(&g_bias2[n0]), bb = __ldg(&g_bias2[n0 + 1]);
        const int r = wm * 16 + g;
        float v0 = acc2[nt][0] + ba, v1 = acc2[nt][1] + bb;
        float v2 = acc2[nt][2] + ba, v3 = acc2[nt][3] + bb;
        if (n0 < Dd) {
            *(float2*)&out[(size_t)(row0 + r) * Dd + n0]     = make_float2(v0, v1);
            *(float2*)&out[(size_t)(row0 + r + 8) * Dd + n0] = make_float2(v2, v3);
        } else {
            const int o = n0 - Dd;
            if (o < NOBS)     { out_yt[(size_t)(row0 + r) * NOBS + o]     = v0;
                                out_yt[(size_t)(row0 + r + 8) * NOBS + o] = v2; }
            if (o + 1 < NOBS) { out_yt[(size_t)(row0 + r) * NOBS + o + 1]     = v1;
                                out_yt[(size_t)(row0 + r + 8) * NOBS + o + 1] = v3; }
        }
    }
}

extern "C" void kernel_launch(void* const* d_in, const int* in_sizes, int n_in,
                              void* d_out, int out_size) {
    const float* z_dyn    = (const float*)d_in[0];
    const float* z_static = (const float*)d_in[1];
    const float* dt       = (const float*)d_in[2];
    const float* ut       = (const float*)d_in[3];
    const float* gates    = (const float*)d_in[4];
    const float* W1       = (const float*)d_in[5];
    const float* b1       = (const float*)d_in[6];
    const float* gamma    = (const float*)d_in[7];
    const float* beta     = (const float*)d_in[8];
    const float* W2       = (const float*)d_in[9];
    const float* b2       = (const float*)d_in[10];
    const float* Bmat     = (const float*)d_in[13];
    const float* Wout     = (const float*)d_in[14];
    const float* Cmat     = (const float*)d_in[15];
    const float* Dm       = (const float*)d_in[16];
    float* out = (float*)d_out;

    pre_w1<<<(HALL * MEAS + 255) / 256, 256>>>(W1, gates);
    pre_M_Mu<<<(NBR * Dd * RH + Dd * UD + 255) / 256, 256>>>(Wout, Bmat);
    pre_P<<<(NBR * Dd * MH + Dd + 255) / 256, 256>>>(W2, b2);
    pre_B2<<<(N2 * K2 + 255) / 256, 256>>>(Cmat, Dm);

    cudaFuncSetAttribute(skolr_mma, cudaFuncAttributeMaxDynamicSharedMemorySize, SMEM_TOTAL);
    skolr_mma<<<BSZ / TM, 256, SMEM_TOTAL>>>(z_dyn, z_static, dt, ut, b1, gamma, beta, out);
}